// round 16
// baseline (speedup 1.0000x reference)
#include <cuda_runtime.h>
#include <cuda_fp16.h>
#include <cstdint>

// Problem constants
#define NPTS   131072
#define DIMK   64
#define KCENT  1024
#define INROW  128

#define THREADS 256          // 8 warps; each warp owns 16 points
#define BM      128          // points per CTA
#define NTILES  (KCENT / 8)  // 128 n8-tiles
#define TPC     16           // tiles per chunk (128 centers)
#define NCHUNK  (NTILES / TPC)           // 8
#define CHUNK_BYTES (TPC * 4 * 32 * 16)  // 32768
#define CN_OFF  (2 * CHUNK_BYTES)        // after the two chunk buffers
#define SMEM_REQ (CN_OFF + KCENT * 4)    // 69632

#define SC      2048.0f          // h1 scale (2^11): keeps fp16 ops normal
#define SCINV   4.8828125e-4f    // 1/2048

__device__ float g_cnorm[KCENT];
__device__ int   g_cmax_bits;    // max ||c||        (float bits, monotone)
__device__ int   g_ch1max_bits;  // max ||c_h1s||    (scaled units)
__device__ int   g_cumax_bits;   // max ||v||  (v = fp16(c_h0 + c_h1s))
__device__ int   g_crmax_bits;   // max ||c_resid||
__device__ int   g_flagcnt;
__device__ int   g_flaglist[NPTS];
// B fragments: [tile(128)][q(4 k16-steps)][lane(32)] x uint4
//   n = tile*8 + lane/4, kb = q*16 + 2*(lane%4)
//   .x = f16x2 h0(c[n][kb]),   h0(c[n][kb+1])
//   .y = f16x2 h0(c[n][kb+8]), h0(c[n][kb+9])
//   .z / .w = same layout for v = fp16(h0 + h1s)
__device__ __align__(16) uint4 g_bfrag[NTILES * 4 * 32];

// ---------------- helpers ----------------
__device__ __forceinline__ unsigned pack_f16(float a, float b) {
    __half2 t = __floats2half2_rn(a, b);   // .x=a (low), .y=b
    return *reinterpret_cast<unsigned*>(&t);
}
// x = f0 + f1*SCINV + r; u = fp16(f0 + f1)  (f1 is the SCALED 2nd term)
__device__ __forceinline__ void split2u(float x, float& f0, float& f1,
                                        float& r, float& u) {
    f0 = __half2float(__float2half_rn(x));
    float t = (x - f0) * SC;               // exact scale by 2^11
    f1 = __half2float(__float2half_rn(t));
    r = (x - f0) - f1 * SCINV;             // exact resid ~2^-22 * x
    u = __half2float(__float2half_rn(f0 + f1));
}
__device__ __forceinline__ void mma_f16(float d[4], const unsigned a[4],
                                        unsigned b0, unsigned b1) {
    asm("mma.sync.aligned.m16n8k16.row.col.f32.f16.f16.f32 "
        "{%0,%1,%2,%3}, {%4,%5,%6,%7}, {%8,%9}, {%0,%1,%2,%3};"
        : "+f"(d[0]), "+f"(d[1]), "+f"(d[2]), "+f"(d[3])
        : "r"(a[0]), "r"(a[1]), "r"(a[2]), "r"(a[3]), "r"(b0), "r"(b1));
}
__device__ __forceinline__ void cp_async16(unsigned smem_addr, const void* g) {
    asm volatile("cp.async.cg.shared.global [%0], [%1], 16;"
                 :: "r"(smem_addr), "l"(g));
}

// ---------------- fused prep: split blob + norms + maxima + reset ----------
__global__ void __launch_bounds__(128)
prep_kernel(const float* __restrict__ centers) {
    __shared__ float s_a[8][16], s_h[8][16], s_r[8][16], s_u[8][16];
    const int tid  = threadIdx.x;
    const int lane = tid & 31;
    const int q    = tid >> 5;          // 0..3
    const int t    = blockIdx.x;        // tile
    const int g    = lane >> 2;         // center within tile, 0..7
    const int cc   = lane & 3;
    const int slot = q * 4 + cc;        // 0..15
    const int n    = t * 8 + g;
    const int kb   = q * 16 + 2 * cc;

    if (t == 0 && tid == 0) g_flagcnt = 0;   // reset per replay

    const float* cr = centers + (size_t)n * DIMK;
    float x0 = __ldg(cr + kb),     x1 = __ldg(cr + kb + 1);
    float x2 = __ldg(cr + kb + 8), x3 = __ldg(cr + kb + 9);

    float f0a, f1a, ra, ua, f0b, f1b, rb, ub;
    float f0c, f1c, rc, uc, f0d, f1d, rd, ud;
    split2u(x0, f0a, f1a, ra, ua);
    split2u(x1, f0b, f1b, rb, ub);
    split2u(x2, f0c, f1c, rc, uc);
    split2u(x3, f0d, f1d, rd, ud);

    uint4 b;
    b.x = pack_f16(f0a, f0b);
    b.y = pack_f16(f0c, f0d);
    b.z = pack_f16(ua, ub);
    b.w = pack_f16(uc, ud);
    g_bfrag[(t * 4 + q) * 32 + lane] = b;

    s_a[g][slot] = x0 * x0 + x1 * x1 + x2 * x2 + x3 * x3;
    s_h[g][slot] = f1a * f1a + f1b * f1b + f1c * f1c + f1d * f1d; // scaled
    s_r[g][slot] = ra * ra + rb * rb + rc * rc + rd * rd;
    s_u[g][slot] = ua * ua + ub * ub + uc * uc + ud * ud;
    __syncthreads();

    if (tid < 8) {   // deterministic fixed-order sums
        float sa = 0.f, sh = 0.f, sr = 0.f, su = 0.f;
        #pragma unroll
        for (int s = 0; s < 16; s++) {
            sa += s_a[tid][s];
            sh += s_h[tid][s];
            sr += s_r[tid][s];
            su += s_u[tid][s];
        }
        g_cnorm[t * 8 + tid] = sa;
        atomicMax(&g_cmax_bits,   __float_as_int(sqrtf(sa) * 1.0002f));
        atomicMax(&g_ch1max_bits, __float_as_int(sqrtf(sh) * 1.0002f));
        atomicMax(&g_cumax_bits,  __float_as_int(sqrtf(su) * 1.0002f));
        atomicMax(&g_crmax_bits,  __float_as_int(sqrtf(sr) * 1.0002f));
    }
}

// ---------------- pass 1: fp16 2-product (hh + uv) GEMM + flag ----------
__global__ void __launch_bounds__(THREADS)
label_mma_kernel(const float* __restrict__ inpt, float* __restrict__ out) {
    extern __shared__ __align__(16) unsigned char sm[];
    const unsigned sbase = (unsigned)__cvta_generic_to_shared(sm);
    float* cn_s = reinterpret_cast<float*>(sm + CN_OFF);

    const int tid  = threadIdx.x;
    const int wid  = tid >> 5;
    const int lane = tid & 31;
    const int r    = lane >> 2;   // 0..7
    const int cc   = lane & 3;    // 0..3
    const int m0   = blockIdx.x * BM;
    const int mrow = m0 + wid * 16;

    // Prefetch chunk 0 (linear copy: blob layout == smem layout)
    {
        const unsigned char* src = (const unsigned char*)g_bfrag;
        #pragma unroll
        for (int j = 0; j < CHUNK_BYTES / (THREADS * 16); j++)
            cp_async16(sbase + tid * 16 + j * (THREADS * 16),
                       src + tid * 16 + j * (THREADS * 16));
        asm volatile("cp.async.commit_group;");
    }

    // Center norms -> smem
    for (int i = tid; i < KCENT; i += THREADS) cn_s[i] = g_cnorm[i];

    // A fragments (h0, u) + per-row norm partials (a, h1s, resid, u)
    unsigned ah0[4][4], au[4][4];
    float sa0 = 0.f, sh10 = 0.f, sr0 = 0.f, su0 = 0.f;
    float sa1 = 0.f, sh11 = 0.f, sr1 = 0.f, su1 = 0.f;
    {
        const float* row0 = inpt + (size_t)(mrow + r) * INROW + DIMK;
        const float* row8 = inpt + (size_t)(mrow + r + 8) * INROW + DIMK;
        #pragma unroll
        for (int q = 0; q < 4; q++) {
            const int kb = q * 16 + 2 * cc;
            float f0[8], f1[8], rr[8], uu[8];
            float xv[8];
            xv[0] = __ldg(row0 + kb);     xv[1] = __ldg(row0 + kb + 1);
            xv[2] = __ldg(row8 + kb);     xv[3] = __ldg(row8 + kb + 1);
            xv[4] = __ldg(row0 + kb + 8); xv[5] = __ldg(row0 + kb + 9);
            xv[6] = __ldg(row8 + kb + 8); xv[7] = __ldg(row8 + kb + 9);
            #pragma unroll
            for (int e = 0; e < 8; e++)
                split2u(xv[e], f0[e], f1[e], rr[e], uu[e]);
            ah0[q][0] = pack_f16(f0[0], f0[1]);
            ah0[q][1] = pack_f16(f0[2], f0[3]);
            ah0[q][2] = pack_f16(f0[4], f0[5]);
            ah0[q][3] = pack_f16(f0[6], f0[7]);
            au[q][0]  = pack_f16(uu[0], uu[1]);
            au[q][1]  = pack_f16(uu[2], uu[3]);
            au[q][2]  = pack_f16(uu[4], uu[5]);
            au[q][3]  = pack_f16(uu[6], uu[7]);
            #pragma unroll
            for (int e = 0; e < 8; e++) {
                // rows: e in {0,1,4,5} -> row r; {2,3,6,7} -> row r+8
                bool isr0 = ((e & 2) == 0);
                float xa = xv[e] * xv[e];
                float xh = f1[e] * f1[e];   // scaled
                float xr = rr[e] * rr[e];
                float xu = uu[e] * uu[e];
                if (isr0) { sa0 += xa; sh10 += xh; sr0 += xr; su0 += xu; }
                else      { sa1 += xa; sh11 += xh; sr1 += xr; su1 += xu; }
            }
        }
        #pragma unroll
        for (int off = 1; off <= 2; off <<= 1) {
            sa0  += __shfl_xor_sync(0xffffffffu, sa0, off);
            sh10 += __shfl_xor_sync(0xffffffffu, sh10, off);
            sr0  += __shfl_xor_sync(0xffffffffu, sr0, off);
            su0  += __shfl_xor_sync(0xffffffffu, su0, off);
            sa1  += __shfl_xor_sync(0xffffffffu, sa1, off);
            sh11 += __shfl_xor_sync(0xffffffffu, sh11, off);
            sr1  += __shfl_xor_sync(0xffffffffu, sr1, off);
            su1  += __shfl_xor_sync(0xffffffffu, su1, off);
        }
    }

    const float INF = __int_as_float(0x7f800000);
    float bd0 = INF, b2d0 = INF, bd1 = INF, b2d1 = INF;
    int   bn0 = 0, bn1 = 0;

    #pragma unroll 1
    for (int c = 0; c < NCHUNK; c++) {
        asm volatile("cp.async.wait_group 0;" ::: "memory");
        __syncthreads();

        if (c + 1 < NCHUNK) {
            const unsigned char* src =
                (const unsigned char*)g_bfrag + (size_t)(c + 1) * CHUNK_BYTES;
            unsigned dst = sbase + ((c + 1) & 1) * CHUNK_BYTES;
            #pragma unroll
            for (int j = 0; j < CHUNK_BYTES / (THREADS * 16); j++)
                cp_async16(dst + tid * 16 + j * (THREADS * 16),
                           src + tid * 16 + j * (THREADS * 16));
            asm volatile("cp.async.commit_group;");
        }

        const unsigned buf = sbase + (c & 1) * CHUNK_BYTES + lane * 16;

        #pragma unroll
        for (int t8 = 0; t8 < TPC; t8 += 2) {    // 2 tiles in flight
            float dA0[4] = {0.f, 0.f, 0.f, 0.f};  // hh
            float dAu[4] = {0.f, 0.f, 0.f, 0.f};  // uv
            float dB0[4] = {0.f, 0.f, 0.f, 0.f};
            float dBu[4] = {0.f, 0.f, 0.f, 0.f};
            #pragma unroll
            for (int q = 0; q < 4; q++) {
                uint4 ba, bb;
                asm volatile("ld.shared.v4.b32 {%0,%1,%2,%3}, [%4];"
                             : "=r"(ba.x), "=r"(ba.y), "=r"(ba.z), "=r"(ba.w)
                             : "r"(buf + (((t8 + 0) * 4 + q) * 32) * 16));
                asm volatile("ld.shared.v4.b32 {%0,%1,%2,%3}, [%4];"
                             : "=r"(bb.x), "=r"(bb.y), "=r"(bb.z), "=r"(bb.w)
                             : "r"(buf + (((t8 + 1) * 4 + q) * 32) * 16));
                mma_f16(dA0, ah0[q], ba.x, ba.y);
                mma_f16(dAu, au[q],  ba.z, ba.w);
                mma_f16(dB0, ah0[q], bb.x, bb.y);
                mma_f16(dBu, au[q],  bb.z, bb.w);
            }
            #pragma unroll
            for (int p = 0; p < 2; p++) {
                const float* d0 = p ? dB0 : dA0;
                const float* du = p ? dBu : dAu;
                const int nbase = c * (TPC * 8) + (t8 + p) * 8 + 2 * cc;
                float2 cn = *reinterpret_cast<const float2*>(cn_s + nbase);
                // dot ~= d0 + SCINV*(du - d0)
                float t0 = fmaf(SCINV, du[0] - d0[0], d0[0]);
                float t1 = fmaf(SCINV, du[1] - d0[1], d0[1]);
                float t2 = fmaf(SCINV, du[2] - d0[2], d0[2]);
                float t3 = fmaf(SCINV, du[3] - d0[3], d0[3]);
                float e0 = fmaf(-2.f, t0, cn.x);
                float e1 = fmaf(-2.f, t1, cn.y);
                float e2 = fmaf(-2.f, t2, cn.x);
                float e3 = fmaf(-2.f, t3, cn.y);
                if (e0 < bd0) { b2d0 = bd0; bd0 = e0; bn0 = nbase; }
                else if (e0 < b2d0) b2d0 = e0;
                if (e1 < bd0) { b2d0 = bd0; bd0 = e1; bn0 = nbase + 1; }
                else if (e1 < b2d0) b2d0 = e1;
                if (e2 < bd1) { b2d1 = bd1; bd1 = e2; bn1 = nbase; }
                else if (e2 < b2d1) b2d1 = e2;
                if (e3 < bd1) { b2d1 = bd1; bd1 = e3; bn1 = nbase + 1; }
                else if (e3 < b2d1) b2d1 = e3;
            }
        }
    }

    // Merge (min, min2) across the 4 cc-lanes (disjoint n-sets)
    #pragma unroll
    for (int off = 1; off <= 2; off <<= 1) {
        float od0 = __shfl_xor_sync(0xffffffffu, bd0, off);
        float o2d0 = __shfl_xor_sync(0xffffffffu, b2d0, off);
        int   on0 = __shfl_xor_sync(0xffffffffu, bn0, off);
        float od1 = __shfl_xor_sync(0xffffffffu, bd1, off);
        float o2d1 = __shfl_xor_sync(0xffffffffu, b2d1, off);
        int   on1 = __shfl_xor_sync(0xffffffffu, bn1, off);
        if (od0 < bd0 || (od0 == bd0 && on0 < bn0)) {
            b2d0 = fminf(bd0, o2d0); bd0 = od0; bn0 = on0;
        } else b2d0 = fminf(b2d0, od0);
        if (od1 < bd1 || (od1 == bd1 && on1 < bn1)) {
            b2d1 = fminf(bd1, o2d1); bd1 = od1; bn1 = on1;
        } else b2d1 = fminf(b2d1, od1);
    }

    if (cc == 0) {
        const float CM  = __int_as_float(g_cmax_bits);
        const float CH1 = __int_as_float(g_ch1max_bits);   // scaled units
        const float CU  = __int_as_float(g_cumax_bits);
        const float CR  = __int_as_float(g_crmax_bits);
        float na0 = sqrtf(sa0), nh0 = sqrtf(sh10), nr0 = sqrtf(sr0),
              nu0 = sqrtf(su0);
        float na1 = sqrtf(sa1), nh1 = sqrtf(sh11), nr1 = sqrtf(sr1),
              nu1 = sqrtf(su1);
        // |dot err| <= SCINV*( ||x_h1s||*||c_h1s||      (uncomputed h1h1)
        //                    + 1.5e-3*||u||*||v||  )    (fp16 rounding of u,v)
        //            + ||x_r||*(||c||+||c_r||) + ||x||*||c_r||   (residuals)
        //            + fp32 accumulation
        float err0 = SCINV * fmaf(1.5e-3f, nu0 * CU, nh0 * CH1)
                   + nr0 * (CM + CR) + na0 * CR + 2e-6f * na0 * CM;
        float err1 = SCINV * fmaf(1.5e-3f, nu1 * CU, nh1 * CH1)
                   + nr1 * (CM + CR) + na1 * CR + 2e-6f * na1 * CM;
        float eps0 = 2.f * err0 + 1e-4f;
        float eps1 = 2.f * err1 + 1e-4f;
        out[mrow + r] = (float)bn0;
        out[mrow + r + 8] = (float)bn1;
        if (b2d0 - bd0 <= eps0) {
            int i = atomicAdd(&g_flagcnt, 1);
            g_flaglist[i] = mrow + r;
        }
        if (b2d1 - bd1 <= eps1) {
            int i = atomicAdd(&g_flagcnt, 1);
            g_flaglist[i] = mrow + r + 8;
        }
    }
}

// ---------------- pass 2: exact fp32 rescan, ONE BLOCK PER FLAGGED POINT ----
__global__ void __launch_bounds__(256)
exact_pass_kernel(const float* __restrict__ inpt,
                  const float* __restrict__ centers,
                  float* __restrict__ out) {
    __shared__ float xs[DIMK];
    __shared__ float swd[8];
    __shared__ int   swn[8];
    const int tid  = threadIdx.x;
    const int lane = tid & 31;
    const int wid  = tid >> 5;
    const int cnt  = g_flagcnt;

    for (int f = blockIdx.x; f < cnt; f += gridDim.x) {
        const int m = g_flaglist[f];
        if (tid < DIMK)
            xs[tid] = __ldg(inpt + (size_t)m * INROW + DIMK + tid);
        __syncthreads();

        float bm = __int_as_float(0x7f800000);
        int   bn = 0;
        #pragma unroll
        for (int j = 0; j < 4; j++) {          // ascending n within thread
            const int n = tid + j * 256;
            const float4* cr = reinterpret_cast<const float4*>(
                centers + (size_t)n * DIMK);
            float s0 = 0.f, s1 = 0.f;          // 2 chains per center
            #pragma unroll
            for (int kk = 0; kk < 16; kk += 2) {
                float4 c0 = __ldg(cr + kk);
                float4 c1 = __ldg(cr + kk + 1);
                s0 = fmaf(xs[kk * 4 + 0], c0.x, s0);
                s0 = fmaf(xs[kk * 4 + 1], c0.y, s0);
                s0 = fmaf(xs[kk * 4 + 2], c0.z, s0);
                s0 = fmaf(xs[kk * 4 + 3], c0.w, s0);
                s1 = fmaf(xs[kk * 4 + 4], c1.x, s1);
                s1 = fmaf(xs[kk * 4 + 5], c1.y, s1);
                s1 = fmaf(xs[kk * 4 + 6], c1.z, s1);
                s1 = fmaf(xs[kk * 4 + 7], c1.w, s1);
            }
            float d = fmaf(-2.f, s0 + s1, g_cnorm[n]);
            if (d < bm) { bm = d; bn = n; }    // strict <: first-min in-thread
        }
        // warp reduce (tie -> lower n)
        #pragma unroll
        for (int off = 16; off > 0; off >>= 1) {
            float od = __shfl_down_sync(0xffffffffu, bm, off);
            int   on = __shfl_down_sync(0xffffffffu, bn, off);
            if (od < bm || (od == bm && on < bn)) { bm = od; bn = on; }
        }
        if (lane == 0) { swd[wid] = bm; swn[wid] = bn; }
        __syncthreads();
        if (tid == 0) {
            float fbm = swd[0];
            int   fbn = swn[0];
            #pragma unroll
            for (int w = 1; w < 8; w++) {
                if (swd[w] < fbm || (swd[w] == fbm && swn[w] < fbn)) {
                    fbm = swd[w]; fbn = swn[w];
                }
            }
            out[m] = (float)fbn;
        }
        __syncthreads();   // xs/swd reused next iteration
    }
}

extern "C" void kernel_launch(void* const* d_in, const int* in_sizes, int n_in,
                              void* d_out, int out_size) {
    // Identify inputs by element count:
    //   inpt: 16777216 elements (unique); centers1: second 65536-elem tensor
    const float* inpt     = nullptr;
    const float* centers1 = nullptr;
    int centers_seen = 0;
    for (int i = 0; i < n_in; i++) {
        if (in_sizes[i] == NPTS * INROW) {
            inpt = (const float*)d_in[i];
        } else if (in_sizes[i] == KCENT * DIMK) {
            centers_seen++;
            if (centers_seen == 2) centers1 = (const float*)d_in[i];
        }
    }
    if (!inpt)     inpt     = (const float*)d_in[0];
    if (!centers1) centers1 = (const float*)d_in[n_in - 1];

    float* out = (float*)d_out;

    cudaFuncSetAttribute(label_mma_kernel,
                         cudaFuncAttributeMaxDynamicSharedMemorySize, SMEM_REQ);

    prep_kernel<<<NTILES, 128>>>(centers1);
    label_mma_kernel<<<NPTS / BM, THREADS, SMEM_REQ>>>(inpt, out);
    exact_pass_kernel<<<2048, 256>>>(inpt, centers1, out);
}

// round 17
// speedup vs baseline: 1.1916x; 1.1916x over previous
#include <cuda_runtime.h>
#include <cuda_fp16.h>
#include <cstdint>

// Problem constants
#define NPTS   131072
#define DIMK   64
#define KCENT  1024
#define INROW  128

#define THREADS 256          // 8 warps; each warp owns 16 points
#define BM      128          // points per CTA
#define NTILES  (KCENT / 8)  // 128 n8-tiles
#define TPC     16           // tiles per chunk (128 centers)
#define NCHUNK  (NTILES / TPC)           // 8
#define CHUNK_BYTES (TPC * 4 * 32 * 16)  // 32768
#define CN_OFF  (2 * CHUNK_BYTES)        // after the two chunk buffers
#define SMEM_REQ (CN_OFF + KCENT * 4)    // 69632

// Scale for the 2nd split term. SC=128 minimizes the certified error:
//   T1 (uncomputed h1h1 term)  ~ SC   * 2^-22 * d
//   T2 (fp16 rounding of u,v)  ~ 1/SC * 2^-10 * d
#define SC      128.0f
#define SCINV   0.0078125f       // 1/128

__device__ float g_cnorm[KCENT];
__device__ int   g_cmax_bits;    // max ||c||        (float bits, monotone)
__device__ int   g_ch1max_bits;  // max ||c_h1s||    (scaled units)
__device__ int   g_cumax_bits;   // max ||v||  (v = fp16(c_h0 + c_h1s))
__device__ int   g_crmax_bits;   // max ||c_resid||
__device__ int   g_flagcnt;
__device__ int   g_flaglist[NPTS];
// B fragments: [tile(128)][q(4 k16-steps)][lane(32)] x uint4
//   n = tile*8 + lane/4, kb = q*16 + 2*(lane%4)
//   .x = f16x2 h0(c[n][kb]),   h0(c[n][kb+1])
//   .y = f16x2 h0(c[n][kb+8]), h0(c[n][kb+9])
//   .z / .w = same layout for v = fp16(h0 + h1s)
__device__ __align__(16) uint4 g_bfrag[NTILES * 4 * 32];

// ---------------- helpers ----------------
__device__ __forceinline__ unsigned pack_f16(float a, float b) {
    __half2 t = __floats2half2_rn(a, b);   // .x=a (low), .y=b
    return *reinterpret_cast<unsigned*>(&t);
}
// x = f0 + f1*SCINV + r; u = fp16(f0 + f1)  (f1 is the SCALED 2nd term)
__device__ __forceinline__ void split2u(float x, float& f0, float& f1,
                                        float& r, float& u) {
    f0 = __half2float(__float2half_rn(x));
    float t = (x - f0) * SC;               // exact scale (power of 2)
    f1 = __half2float(__float2half_rn(t));
    r = (x - f0) - f1 * SCINV;             // exact resid (captures any flush)
    u = __half2float(__float2half_rn(f0 + f1));
}
__device__ __forceinline__ void mma_f16(float d[4], const unsigned a[4],
                                        unsigned b0, unsigned b1) {
    asm("mma.sync.aligned.m16n8k16.row.col.f32.f16.f16.f32 "
        "{%0,%1,%2,%3}, {%4,%5,%6,%7}, {%8,%9}, {%0,%1,%2,%3};"
        : "+f"(d[0]), "+f"(d[1]), "+f"(d[2]), "+f"(d[3])
        : "r"(a[0]), "r"(a[1]), "r"(a[2]), "r"(a[3]), "r"(b0), "r"(b1));
}
__device__ __forceinline__ void cp_async16(unsigned smem_addr, const void* g) {
    asm volatile("cp.async.cg.shared.global [%0], [%1], 16;"
                 :: "r"(smem_addr), "l"(g));
}

// ---------------- fused prep: split blob + norms + maxima + reset ----------
__global__ void __launch_bounds__(128)
prep_kernel(const float* __restrict__ centers) {
    __shared__ float s_a[8][16], s_h[8][16], s_r[8][16], s_u[8][16];
    const int tid  = threadIdx.x;
    const int lane = tid & 31;
    const int q    = tid >> 5;          // 0..3
    const int t    = blockIdx.x;        // tile
    const int g    = lane >> 2;         // center within tile, 0..7
    const int cc   = lane & 3;
    const int slot = q * 4 + cc;        // 0..15
    const int n    = t * 8 + g;
    const int kb   = q * 16 + 2 * cc;

    if (t == 0 && tid == 0) g_flagcnt = 0;   // reset per replay

    const float* cr = centers + (size_t)n * DIMK;
    float x0 = __ldg(cr + kb),     x1 = __ldg(cr + kb + 1);
    float x2 = __ldg(cr + kb + 8), x3 = __ldg(cr + kb + 9);

    float f0a, f1a, ra, ua, f0b, f1b, rb, ub;
    float f0c, f1c, rc, uc, f0d, f1d, rd, ud;
    split2u(x0, f0a, f1a, ra, ua);
    split2u(x1, f0b, f1b, rb, ub);
    split2u(x2, f0c, f1c, rc, uc);
    split2u(x3, f0d, f1d, rd, ud);

    uint4 b;
    b.x = pack_f16(f0a, f0b);
    b.y = pack_f16(f0c, f0d);
    b.z = pack_f16(ua, ub);
    b.w = pack_f16(uc, ud);
    g_bfrag[(t * 4 + q) * 32 + lane] = b;

    s_a[g][slot] = x0 * x0 + x1 * x1 + x2 * x2 + x3 * x3;
    s_h[g][slot] = f1a * f1a + f1b * f1b + f1c * f1c + f1d * f1d; // scaled
    s_r[g][slot] = ra * ra + rb * rb + rc * rc + rd * rd;
    s_u[g][slot] = ua * ua + ub * ub + uc * uc + ud * ud;
    __syncthreads();

    if (tid < 8) {   // deterministic fixed-order sums
        float sa = 0.f, sh = 0.f, sr = 0.f, su = 0.f;
        #pragma unroll
        for (int s = 0; s < 16; s++) {
            sa += s_a[tid][s];
            sh += s_h[tid][s];
            sr += s_r[tid][s];
            su += s_u[tid][s];
        }
        g_cnorm[t * 8 + tid] = sa;
        atomicMax(&g_cmax_bits,   __float_as_int(sqrtf(sa) * 1.0002f));
        atomicMax(&g_ch1max_bits, __float_as_int(sqrtf(sh) * 1.0002f));
        atomicMax(&g_cumax_bits,  __float_as_int(sqrtf(su) * 1.0002f));
        atomicMax(&g_crmax_bits,  __float_as_int(sqrtf(sr) * 1.0002f));
    }
}

// ---------------- pass 1: fp16 2-product (hh + uv) GEMM + flag ----------
__global__ void __launch_bounds__(THREADS)
label_mma_kernel(const float* __restrict__ inpt, float* __restrict__ out) {
    extern __shared__ __align__(16) unsigned char sm[];
    const unsigned sbase = (unsigned)__cvta_generic_to_shared(sm);
    float* cn_s = reinterpret_cast<float*>(sm + CN_OFF);

    const int tid  = threadIdx.x;
    const int wid  = tid >> 5;
    const int lane = tid & 31;
    const int r    = lane >> 2;   // 0..7
    const int cc   = lane & 3;    // 0..3
    const int m0   = blockIdx.x * BM;
    const int mrow = m0 + wid * 16;

    // Prefetch chunk 0 (linear copy: blob layout == smem layout)
    {
        const unsigned char* src = (const unsigned char*)g_bfrag;
        #pragma unroll
        for (int j = 0; j < CHUNK_BYTES / (THREADS * 16); j++)
            cp_async16(sbase + tid * 16 + j * (THREADS * 16),
                       src + tid * 16 + j * (THREADS * 16));
        asm volatile("cp.async.commit_group;");
    }

    // Center norms -> smem
    for (int i = tid; i < KCENT; i += THREADS) cn_s[i] = g_cnorm[i];

    // A fragments (h0, u) + per-row norm partials (a, h1s, resid, u)
    unsigned ah0[4][4], au[4][4];
    float sa0 = 0.f, sh10 = 0.f, sr0 = 0.f, su0 = 0.f;
    float sa1 = 0.f, sh11 = 0.f, sr1 = 0.f, su1 = 0.f;
    {
        const float* row0 = inpt + (size_t)(mrow + r) * INROW + DIMK;
        const float* row8 = inpt + (size_t)(mrow + r + 8) * INROW + DIMK;
        #pragma unroll
        for (int q = 0; q < 4; q++) {
            const int kb = q * 16 + 2 * cc;
            float f0[8], f1[8], rr[8], uu[8];
            float xv[8];
            xv[0] = __ldg(row0 + kb);     xv[1] = __ldg(row0 + kb + 1);
            xv[2] = __ldg(row8 + kb);     xv[3] = __ldg(row8 + kb + 1);
            xv[4] = __ldg(row0 + kb + 8); xv[5] = __ldg(row0 + kb + 9);
            xv[6] = __ldg(row8 + kb + 8); xv[7] = __ldg(row8 + kb + 9);
            #pragma unroll
            for (int e = 0; e < 8; e++)
                split2u(xv[e], f0[e], f1[e], rr[e], uu[e]);
            ah0[q][0] = pack_f16(f0[0], f0[1]);
            ah0[q][1] = pack_f16(f0[2], f0[3]);
            ah0[q][2] = pack_f16(f0[4], f0[5]);
            ah0[q][3] = pack_f16(f0[6], f0[7]);
            au[q][0]  = pack_f16(uu[0], uu[1]);
            au[q][1]  = pack_f16(uu[2], uu[3]);
            au[q][2]  = pack_f16(uu[4], uu[5]);
            au[q][3]  = pack_f16(uu[6], uu[7]);
            #pragma unroll
            for (int e = 0; e < 8; e++) {
                // rows: e in {0,1,4,5} -> row r; {2,3,6,7} -> row r+8
                bool isr0 = ((e & 2) == 0);
                float xa = xv[e] * xv[e];
                float xh = f1[e] * f1[e];   // scaled
                float xr = rr[e] * rr[e];
                float xu = uu[e] * uu[e];
                if (isr0) { sa0 += xa; sh10 += xh; sr0 += xr; su0 += xu; }
                else      { sa1 += xa; sh11 += xh; sr1 += xr; su1 += xu; }
            }
        }
        #pragma unroll
        for (int off = 1; off <= 2; off <<= 1) {
            sa0  += __shfl_xor_sync(0xffffffffu, sa0, off);
            sh10 += __shfl_xor_sync(0xffffffffu, sh10, off);
            sr0  += __shfl_xor_sync(0xffffffffu, sr0, off);
            su0  += __shfl_xor_sync(0xffffffffu, su0, off);
            sa1  += __shfl_xor_sync(0xffffffffu, sa1, off);
            sh11 += __shfl_xor_sync(0xffffffffu, sh11, off);
            sr1  += __shfl_xor_sync(0xffffffffu, sr1, off);
            su1  += __shfl_xor_sync(0xffffffffu, su1, off);
        }
    }

    const float INF = __int_as_float(0x7f800000);
    float bd0 = INF, b2d0 = INF, bd1 = INF, b2d1 = INF;
    int   bn0 = 0, bn1 = 0;

    #pragma unroll 1
    for (int c = 0; c < NCHUNK; c++) {
        asm volatile("cp.async.wait_group 0;" ::: "memory");
        __syncthreads();

        if (c + 1 < NCHUNK) {
            const unsigned char* src =
                (const unsigned char*)g_bfrag + (size_t)(c + 1) * CHUNK_BYTES;
            unsigned dst = sbase + ((c + 1) & 1) * CHUNK_BYTES;
            #pragma unroll
            for (int j = 0; j < CHUNK_BYTES / (THREADS * 16); j++)
                cp_async16(dst + tid * 16 + j * (THREADS * 16),
                           src + tid * 16 + j * (THREADS * 16));
            asm volatile("cp.async.commit_group;");
        }

        const unsigned buf = sbase + (c & 1) * CHUNK_BYTES + lane * 16;

        #pragma unroll
        for (int t8 = 0; t8 < TPC; t8 += 2) {    // 2 tiles in flight
            float dA0[4] = {0.f, 0.f, 0.f, 0.f};  // hh
            float dAu[4] = {0.f, 0.f, 0.f, 0.f};  // uv
            float dB0[4] = {0.f, 0.f, 0.f, 0.f};
            float dBu[4] = {0.f, 0.f, 0.f, 0.f};
            #pragma unroll
            for (int q = 0; q < 4; q++) {
                uint4 ba, bb;
                asm volatile("ld.shared.v4.b32 {%0,%1,%2,%3}, [%4];"
                             : "=r"(ba.x), "=r"(ba.y), "=r"(ba.z), "=r"(ba.w)
                             : "r"(buf + (((t8 + 0) * 4 + q) * 32) * 16));
                asm volatile("ld.shared.v4.b32 {%0,%1,%2,%3}, [%4];"
                             : "=r"(bb.x), "=r"(bb.y), "=r"(bb.z), "=r"(bb.w)
                             : "r"(buf + (((t8 + 1) * 4 + q) * 32) * 16));
                mma_f16(dA0, ah0[q], ba.x, ba.y);
                mma_f16(dAu, au[q],  ba.z, ba.w);
                mma_f16(dB0, ah0[q], bb.x, bb.y);
                mma_f16(dBu, au[q],  bb.z, bb.w);
            }
            #pragma unroll
            for (int p = 0; p < 2; p++) {
                const float* d0 = p ? dB0 : dA0;
                const float* du = p ? dBu : dAu;
                const int nbase = c * (TPC * 8) + (t8 + p) * 8 + 2 * cc;
                float2 cn = *reinterpret_cast<const float2*>(cn_s + nbase);
                // dot ~= d0 + SCINV*(du - d0)
                float t0 = fmaf(SCINV, du[0] - d0[0], d0[0]);
                float t1 = fmaf(SCINV, du[1] - d0[1], d0[1]);
                float t2 = fmaf(SCINV, du[2] - d0[2], d0[2]);
                float t3 = fmaf(SCINV, du[3] - d0[3], d0[3]);
                float e0 = fmaf(-2.f, t0, cn.x);
                float e1 = fmaf(-2.f, t1, cn.y);
                float e2 = fmaf(-2.f, t2, cn.x);
                float e3 = fmaf(-2.f, t3, cn.y);
                if (e0 < bd0) { b2d0 = bd0; bd0 = e0; bn0 = nbase; }
                else if (e0 < b2d0) b2d0 = e0;
                if (e1 < bd0) { b2d0 = bd0; bd0 = e1; bn0 = nbase + 1; }
                else if (e1 < b2d0) b2d0 = e1;
                if (e2 < bd1) { b2d1 = bd1; bd1 = e2; bn1 = nbase; }
                else if (e2 < b2d1) b2d1 = e2;
                if (e3 < bd1) { b2d1 = bd1; bd1 = e3; bn1 = nbase + 1; }
                else if (e3 < b2d1) b2d1 = e3;
            }
        }
    }

    // Merge (min, min2) across the 4 cc-lanes (disjoint n-sets)
    #pragma unroll
    for (int off = 1; off <= 2; off <<= 1) {
        float od0 = __shfl_xor_sync(0xffffffffu, bd0, off);
        float o2d0 = __shfl_xor_sync(0xffffffffu, b2d0, off);
        int   on0 = __shfl_xor_sync(0xffffffffu, bn0, off);
        float od1 = __shfl_xor_sync(0xffffffffu, bd1, off);
        float o2d1 = __shfl_xor_sync(0xffffffffu, b2d1, off);
        int   on1 = __shfl_xor_sync(0xffffffffu, bn1, off);
        if (od0 < bd0 || (od0 == bd0 && on0 < bn0)) {
            b2d0 = fminf(bd0, o2d0); bd0 = od0; bn0 = on0;
        } else b2d0 = fminf(b2d0, od0);
        if (od1 < bd1 || (od1 == bd1 && on1 < bn1)) {
            b2d1 = fminf(bd1, o2d1); bd1 = od1; bn1 = on1;
        } else b2d1 = fminf(b2d1, od1);
    }

    if (cc == 0) {
        const float CM  = __int_as_float(g_cmax_bits);
        const float CH1 = __int_as_float(g_ch1max_bits);   // scaled units
        const float CU  = __int_as_float(g_cumax_bits);
        const float CR  = __int_as_float(g_crmax_bits);
        float na0 = sqrtf(sa0), nh0 = sqrtf(sh10), nr0 = sqrtf(sr0),
              nu0 = sqrtf(su0);
        float na1 = sqrtf(sa1), nh1 = sqrtf(sh11), nr1 = sqrtf(sr1),
              nu1 = sqrtf(su1);
        // |dot err| <= SCINV*( ||x_h1s||*||c_h1s||      (uncomputed h1h1)
        //                    + 1.5e-3*||u||*||v||  )    (fp16 rounding of u,v)
        //            + ||x_r||*(||c||+||c_r||) + ||x||*||c_r||   (residuals)
        //            + fp32 accumulation
        float err0 = SCINV * fmaf(1.5e-3f, nu0 * CU, nh0 * CH1)
                   + nr0 * (CM + CR) + na0 * CR + 2e-6f * na0 * CM;
        float err1 = SCINV * fmaf(1.5e-3f, nu1 * CU, nh1 * CH1)
                   + nr1 * (CM + CR) + na1 * CR + 2e-6f * na1 * CM;
        float eps0 = 2.f * err0 + 1e-4f;
        float eps1 = 2.f * err1 + 1e-4f;
        out[mrow + r] = (float)bn0;
        out[mrow + r + 8] = (float)bn1;
        if (b2d0 - bd0 <= eps0) {
            int i = atomicAdd(&g_flagcnt, 1);
            g_flaglist[i] = mrow + r;
        }
        if (b2d1 - bd1 <= eps1) {
            int i = atomicAdd(&g_flagcnt, 1);
            g_flaglist[i] = mrow + r + 8;
        }
    }
}

// ---------------- pass 2: exact fp32 rescan, ONE BLOCK PER FLAGGED POINT ----
__global__ void __launch_bounds__(256)
exact_pass_kernel(const float* __restrict__ inpt,
                  const float* __restrict__ centers,
                  float* __restrict__ out) {
    __shared__ float xs[DIMK];
    __shared__ float swd[8];
    __shared__ int   swn[8];
    const int tid  = threadIdx.x;
    const int lane = tid & 31;
    const int wid  = tid >> 5;
    const int cnt  = g_flagcnt;

    for (int f = blockIdx.x; f < cnt; f += gridDim.x) {
        const int m = g_flaglist[f];
        if (tid < DIMK)
            xs[tid] = __ldg(inpt + (size_t)m * INROW + DIMK + tid);
        __syncthreads();

        float bm = __int_as_float(0x7f800000);
        int   bn = 0;
        #pragma unroll
        for (int j = 0; j < 4; j++) {          // ascending n within thread
            const int n = tid + j * 256;
            const float4* cr = reinterpret_cast<const float4*>(
                centers + (size_t)n * DIMK);
            float s0 = 0.f, s1 = 0.f;          // 2 chains per center
            #pragma unroll
            for (int kk = 0; kk < 16; kk += 2) {
                float4 c0 = __ldg(cr + kk);
                float4 c1 = __ldg(cr + kk + 1);
                s0 = fmaf(xs[kk * 4 + 0], c0.x, s0);
                s0 = fmaf(xs[kk * 4 + 1], c0.y, s0);
                s0 = fmaf(xs[kk * 4 + 2], c0.z, s0);
                s0 = fmaf(xs[kk * 4 + 3], c0.w, s0);
                s1 = fmaf(xs[kk * 4 + 4], c1.x, s1);
                s1 = fmaf(xs[kk * 4 + 5], c1.y, s1);
                s1 = fmaf(xs[kk * 4 + 6], c1.z, s1);
                s1 = fmaf(xs[kk * 4 + 7], c1.w, s1);
            }
            float d = fmaf(-2.f, s0 + s1, g_cnorm[n]);
            if (d < bm) { bm = d; bn = n; }    // strict <: first-min in-thread
        }
        // warp reduce (tie -> lower n)
        #pragma unroll
        for (int off = 16; off > 0; off >>= 1) {
            float od = __shfl_down_sync(0xffffffffu, bm, off);
            int   on = __shfl_down_sync(0xffffffffu, bn, off);
            if (od < bm || (od == bm && on < bn)) { bm = od; bn = on; }
        }
        if (lane == 0) { swd[wid] = bm; swn[wid] = bn; }
        __syncthreads();
        if (tid == 0) {
            float fbm = swd[0];
            int   fbn = swn[0];
            #pragma unroll
            for (int w = 1; w < 8; w++) {
                if (swd[w] < fbm || (swd[w] == fbm && swn[w] < fbn)) {
                    fbm = swd[w]; fbn = swn[w];
                }
            }
            out[m] = (float)fbn;
        }
        __syncthreads();   // xs/swd reused next iteration
    }
}

extern "C" void kernel_launch(void* const* d_in, const int* in_sizes, int n_in,
                              void* d_out, int out_size) {
    // Identify inputs by element count:
    //   inpt: 16777216 elements (unique); centers1: second 65536-elem tensor
    const float* inpt     = nullptr;
    const float* centers1 = nullptr;
    int centers_seen = 0;
    for (int i = 0; i < n_in; i++) {
        if (in_sizes[i] == NPTS * INROW) {
            inpt = (const float*)d_in[i];
        } else if (in_sizes[i] == KCENT * DIMK) {
            centers_seen++;
            if (centers_seen == 2) centers1 = (const float*)d_in[i];
        }
    }
    if (!inpt)     inpt     = (const float*)d_in[0];
    if (!centers1) centers1 = (const float*)d_in[n_in - 1];

    float* out = (float*)d_out;

    cudaFuncSetAttribute(label_mma_kernel,
                         cudaFuncAttributeMaxDynamicSharedMemorySize, SMEM_REQ);

    prep_kernel<<<NTILES, 128>>>(centers1);
    label_mma_kernel<<<NPTS / BM, THREADS, SMEM_REQ>>>(inpt, out);
    exact_pass_kernel<<<2048, 256>>>(inpt, centers1, out);
}